// round 1
// baseline (speedup 1.0000x reference)
#include <cuda_runtime.h>
#include <cstddef>

#define NN   50000
#define RR   3
#define EE   800000
#define HIDD 128

// ---------------- static scratch (no cudaMalloc allowed) ----------------
__device__ int   g_outdeg[RR * NN];
__device__ int   g_indeg [RR * NN];
__device__ float g_rout  [RR * NN];
__device__ float g_rin   [RR * NN];
__device__ int   g_rowptr[RR * (NN + 1)];
__device__ int   g_cursor[RR * (NN + 1)];
__device__ int   g_cols  [RR * EE];
__device__ float g_wts   [RR * EE];
__device__ float g_z     [(size_t)NN * RR * HIDD];   // [n][r*128+c] == [n][384]
__device__ float g_h     [2][(size_t)NN * HIDD];

// ---------------- preprocessing kernels ----------------
__global__ void zero_deg_kernel() {
    int i = blockIdx.x * blockDim.x + threadIdx.x;
    if (i < RR * NN) { g_outdeg[i] = 0; g_indeg[i] = 0; }
}

__global__ void deg_kernel(const int* __restrict__ src, const int* __restrict__ dst) {
    int i = blockIdx.x * blockDim.x + threadIdx.x;
    if (i >= RR * EE) return;
    int r = i / EE;
    atomicAdd(&g_outdeg[r * NN + src[i]], 1);
    atomicAdd(&g_indeg [r * NN + dst[i]], 1);
}

__global__ void rsqrt_kernel() {
    int i = blockIdx.x * blockDim.x + threadIdx.x;
    if (i >= RR * NN) return;
    g_rout[i] = rsqrtf(fmaxf((float)g_outdeg[i], 1.0f));
    g_rin [i] = rsqrtf(fmaxf((float)g_indeg [i], 1.0f));
}

// one block per relation: exclusive scan of in-degrees -> CSR row_ptr (+cursor copy)
__global__ void scan_kernel() {
    const int T = 1024;
    int r = blockIdx.x;
    __shared__ int warpsums[32];
    __shared__ int s_carry;
    int tid = threadIdx.x, lane = tid & 31, wid = tid >> 5;
    if (tid == 0) s_carry = 0;
    __syncthreads();
    for (int base = 0; base < NN; base += T) {
        int i = base + tid;
        int v = (i < NN) ? g_indeg[r * NN + i] : 0;
        int inc = v;
        #pragma unroll
        for (int o = 1; o < 32; o <<= 1) {
            int t = __shfl_up_sync(0xFFFFFFFFu, inc, o);
            if (lane >= o) inc += t;
        }
        if (lane == 31) warpsums[wid] = inc;
        __syncthreads();
        if (wid == 0) {
            int ws = warpsums[lane];
            #pragma unroll
            for (int o = 1; o < 32; o <<= 1) {
                int t = __shfl_up_sync(0xFFFFFFFFu, ws, o);
                if (lane >= o) ws += t;
            }
            warpsums[lane] = ws;
        }
        __syncthreads();
        int offset = s_carry + ((wid > 0) ? warpsums[wid - 1] : 0);
        int excl = offset + inc - v;
        if (i < NN) {
            g_rowptr[r * (NN + 1) + i] = excl;
            g_cursor[r * (NN + 1) + i] = excl;
        }
        __syncthreads();
        if (tid == T - 1) s_carry = offset + inc;
        __syncthreads();
    }
    if (tid == 0) g_rowptr[r * (NN + 1) + NN] = s_carry;
}

__global__ void fill_kernel(const int* __restrict__ src, const int* __restrict__ dst) {
    int i = blockIdx.x * blockDim.x + threadIdx.x;
    if (i >= RR * EE) return;
    int r = i / EE;
    int d = dst[i];
    int s = src[i];
    int pos = atomicAdd(&g_cursor[r * (NN + 1) + d], 1);
    g_cols[(size_t)r * EE + pos] = s;
    g_wts [(size_t)r * EE + pos] = g_rout[r * NN + s];
}

// ---------------- SpMM: one warp per (relation, dst-row) ----------------
// z[n][r*128 + c] = rin[r][n] * sum_e wts[e] * h[cols[e]][c]
__global__ void spmm_kernel(const float* __restrict__ xin, int in_sel) {
    int gw   = (blockIdx.x * blockDim.x + threadIdx.x) >> 5;
    int lane = threadIdx.x & 31;
    if (gw >= RR * NN) return;
    int r = gw / NN;
    int n = gw - r * NN;

    const float* hin = (in_sel < 0) ? xin : g_h[in_sel];
    const float4* h4 = (const float4*)hin;
    const int*   cols = g_cols + (size_t)r * EE;
    const float* wts  = g_wts  + (size_t)r * EE;

    int start = g_rowptr[r * (NN + 1) + n];
    int end   = g_rowptr[r * (NN + 1) + n + 1];

    float4 acc = make_float4(0.f, 0.f, 0.f, 0.f);
    int e = start;
    for (; e + 4 <= end; e += 4) {
        int s0 = cols[e], s1 = cols[e + 1], s2 = cols[e + 2], s3 = cols[e + 3];
        float w0 = wts[e], w1 = wts[e + 1], w2 = wts[e + 2], w3 = wts[e + 3];
        float4 v0 = h4[(size_t)s0 * 32 + lane];
        float4 v1 = h4[(size_t)s1 * 32 + lane];
        float4 v2 = h4[(size_t)s2 * 32 + lane];
        float4 v3 = h4[(size_t)s3 * 32 + lane];
        acc.x = fmaf(w0, v0.x, acc.x); acc.y = fmaf(w0, v0.y, acc.y);
        acc.z = fmaf(w0, v0.z, acc.z); acc.w = fmaf(w0, v0.w, acc.w);
        acc.x = fmaf(w1, v1.x, acc.x); acc.y = fmaf(w1, v1.y, acc.y);
        acc.z = fmaf(w1, v1.z, acc.z); acc.w = fmaf(w1, v1.w, acc.w);
        acc.x = fmaf(w2, v2.x, acc.x); acc.y = fmaf(w2, v2.y, acc.y);
        acc.z = fmaf(w2, v2.z, acc.z); acc.w = fmaf(w2, v2.w, acc.w);
        acc.x = fmaf(w3, v3.x, acc.x); acc.y = fmaf(w3, v3.y, acc.y);
        acc.z = fmaf(w3, v3.z, acc.z); acc.w = fmaf(w3, v3.w, acc.w);
    }
    for (; e < end; e++) {
        int s = cols[e]; float w = wts[e];
        float4 v = h4[(size_t)s * 32 + lane];
        acc.x = fmaf(w, v.x, acc.x); acc.y = fmaf(w, v.y, acc.y);
        acc.z = fmaf(w, v.z, acc.z); acc.w = fmaf(w, v.w, acc.w);
    }
    float ri = g_rin[r * NN + n];
    acc.x *= ri; acc.y *= ri; acc.z *= ri; acc.w *= ri;
    ((float4*)g_z)[((size_t)n * RR + r) * 32 + lane] = acc;
}

// ---------------- SGEMM: C[M,BN] = (A[M,K] @ B[K,BN] + sum_bias) * alpha ----------------
// a_sel: 0/1 -> g_h[a_sel], 2 -> g_z      o_sel: 0/1 -> g_h[o_sel], 2 -> Cext
template <int BN, int NT>
__global__ __launch_bounds__(NT)
void gemm_kernel(int a_sel, const float* __restrict__ B,
                 const float* __restrict__ bias, int biasRows,
                 int o_sel, float* __restrict__ Cext,
                 int M, int K, float alpha, int leaky) {
    const int BM = 128, BK = 16, TM = 8, TN = 8;
    const float* A = (a_sel == 2) ? g_z : g_h[a_sel];
    float*       C = (o_sel == 2) ? Cext : g_h[o_sel];

    __shared__ float As[BK][BM + 4];
    __shared__ float Bs[BK][BN];

    int tid  = threadIdx.x;
    int trow = tid / (BN / TN);
    int tcol = tid % (BN / TN);
    int blockRow = blockIdx.x * BM;

    float acc[TM][TN];
    #pragma unroll
    for (int i = 0; i < TM; i++)
        #pragma unroll
        for (int j = 0; j < TN; j++) acc[i][j] = 0.f;

    const int AV = BM * BK / 4;   // float4 slots in A tile
    const int BV = BK * BN / 4;

    for (int k0 = 0; k0 < K; k0 += BK) {
        #pragma unroll
        for (int i = 0; i < AV / NT; i++) {
            int v   = tid + i * NT;
            int row = v / (BK / 4);
            int kq  = v % (BK / 4);
            int gr  = blockRow + row;
            float4 val = make_float4(0.f, 0.f, 0.f, 0.f);
            if (gr < M) val = *(const float4*)(A + (size_t)gr * K + k0 + kq * 4);
            As[kq * 4 + 0][row] = val.x;
            As[kq * 4 + 1][row] = val.y;
            As[kq * 4 + 2][row] = val.z;
            As[kq * 4 + 3][row] = val.w;
        }
        #pragma unroll
        for (int i = 0; i < BV / NT; i++) {
            int v  = tid + i * NT;
            int kr = v / (BN / 4);
            int jq = v % (BN / 4);
            *(float4*)&Bs[kr][jq * 4] = *(const float4*)(B + (size_t)(k0 + kr) * BN + jq * 4);
        }
        __syncthreads();
        #pragma unroll
        for (int kk = 0; kk < BK; kk++) {
            float a[TM], b[TN];
            #pragma unroll
            for (int j = 0; j < TM; j += 4) *(float4*)&a[j] = *(const float4*)&As[kk][trow * TM + j];
            #pragma unroll
            for (int j = 0; j < TN; j += 4) *(float4*)&b[j] = *(const float4*)&Bs[kk][tcol * TN + j];
            #pragma unroll
            for (int ii = 0; ii < TM; ii++)
                #pragma unroll
                for (int jj = 0; jj < TN; jj++)
                    acc[ii][jj] = fmaf(a[ii], b[jj], acc[ii][jj]);
        }
        __syncthreads();
    }

    float bsum[TN];
    #pragma unroll
    for (int jj = 0; jj < TN; jj++) {
        int col = tcol * TN + jj;
        float s = 0.f;
        for (int rr = 0; rr < biasRows; rr++) s += bias[rr * BN + col];
        bsum[jj] = s;
    }
    #pragma unroll
    for (int ii = 0; ii < TM; ii++) {
        int gr = blockRow + trow * TM + ii;
        if (gr >= M) continue;
        float o[TN];
        #pragma unroll
        for (int jj = 0; jj < TN; jj++) {
            float v = (acc[ii][jj] + bsum[jj]) * alpha;
            if (leaky && v < 0.f) v *= 0.01f;
            o[jj] = v;
        }
        #pragma unroll
        for (int j = 0; j < TN; j += 4)
            *(float4*)(C + (size_t)gr * BN + tcol * TN + j) = *(float4*)&o[j];
    }
}

// ---------------- launcher ----------------
extern "C" void kernel_launch(void* const* d_in, const int* in_sizes, int n_in,
                              void* d_out, int out_size) {
    const float* x    = (const float*)d_in[0];
    const int*   esrc = (const int*)  d_in[1];
    const int*   edst = (const int*)  d_in[2];
    const float* W0   = (const float*)d_in[3];
    const float* b0   = (const float*)d_in[4];
    const float* Wl   = (const float*)d_in[5];
    const float* bl   = (const float*)d_in[6];
    const float* Wout = (const float*)d_in[7];
    const float* bout = (const float*)d_in[8];
    float* out = (float*)d_out;

    // ---- preprocessing (replayed every graph launch; deterministic work) ----
    zero_deg_kernel<<<(RR * NN + 255) / 256, 256>>>();
    deg_kernel<<<(RR * EE + 255) / 256, 256>>>(esrc, edst);
    rsqrt_kernel<<<(RR * NN + 255) / 256, 256>>>();
    scan_kernel<<<RR, 1024>>>();
    fill_kernel<<<(RR * EE + 255) / 256, 256>>>(esrc, edst);

    const int spmm_blocks = (RR * NN * 32 + 255) / 256;
    const int gemm_blocks = (NN + 127) / 128;
    const float inv_r = 1.0f / (float)RR;

    // layer 0: x -> h[0], leaky
    spmm_kernel<<<spmm_blocks, 256>>>(x, -1);
    gemm_kernel<128, 256><<<gemm_blocks, 256>>>(2, W0, b0, RR, 0, nullptr,
                                                NN, RR * HIDD, inv_r, 1);
    // layers 1..4: h[cur] -> h[cur^1], leaky except last
    int cur = 0;
    for (int l = 0; l < 4; l++) {
        spmm_kernel<<<spmm_blocks, 256>>>(nullptr, cur);
        gemm_kernel<128, 256><<<gemm_blocks, 256>>>(
            2, Wl + (size_t)l * RR * HIDD * HIDD, bl + (size_t)l * RR * HIDD, RR,
            cur ^ 1, nullptr, NN, RR * HIDD, inv_r, (l != 3) ? 1 : 0);
        cur ^= 1;
    }
    // final linear: h[cur] @ Wout + bout -> d_out
    gemm_kernel<64, 128><<<gemm_blocks, 128>>>(cur, Wout, bout, 1, 2, out,
                                               NN, HIDD, 1.0f, 0);
}

// round 2
// speedup vs baseline: 1.0373x; 1.0373x over previous
#include <cuda_runtime.h>
#include <cuda_fp16.h>
#include <cstddef>

#define NN   50000
#define RR   3
#define EE   800000
#define HIDD 128
#define SB   256
#define NBLK ((NN + SB - 1) / SB)   // 196

// ---------------- static scratch (no cudaMalloc allowed) ----------------
__device__ int    g_outdeg[RR * NN];
__device__ int    g_indeg [RR * NN];
__device__ float  g_rout  [RR * NN];
__device__ float  g_rin   [RR * NN];
__device__ int    g_rowptr[RR * (NN + 1)];
__device__ int    g_cursor[RR * (NN + 1)];
__device__ int    g_bsum  [RR][NBLK];
__device__ int    g_boff  [RR][NBLK];
__device__ int    g_cols  [RR * EE];
__device__ float  g_wts   [RR * EE];
__device__ float  g_z     [(size_t)NN * RR * HIDD];   // [n][r*128+c]
__device__ float  g_h     [2][(size_t)NN * HIDD];     // fp32 (GEMM A operand)
__device__ __half g_hh    [2][(size_t)NN * HIDD];     // fp16 mirror (SpMM gather)
__device__ __half g_xh    [(size_t)NN * HIDD];        // fp16 copy of x

// ---------------- preprocessing ----------------
__global__ void zero_deg_kernel() {
    int i = blockIdx.x * blockDim.x + threadIdx.x;
    if (i < RR * NN) { g_outdeg[i] = 0; g_indeg[i] = 0; }
}

__global__ void deg_kernel(const int* __restrict__ src, const int* __restrict__ dst) {
    int i = blockIdx.x * blockDim.x + threadIdx.x;
    if (i >= RR * EE) return;
    int r = i / EE;
    atomicAdd(&g_outdeg[r * NN + src[i]], 1);
    atomicAdd(&g_indeg [r * NN + dst[i]], 1);
}

__global__ void rsqrt_kernel() {
    int i = blockIdx.x * blockDim.x + threadIdx.x;
    if (i >= RR * NN) return;
    g_rout[i] = rsqrtf(fmaxf((float)g_outdeg[i], 1.0f));
    g_rin [i] = rsqrtf(fmaxf((float)g_indeg [i], 1.0f));
}

__global__ void xconv_kernel(const float* __restrict__ x) {
    int i = blockIdx.x * blockDim.x + threadIdx.x;
    if (i < NN * HIDD / 2) {
        float2 v = ((const float2*)x)[i];
        ((__half2*)g_xh)[i] = __floats2half2_rn(v.x, v.y);
    }
}

__device__ __forceinline__ int warp_incl_scan(int v, int lane) {
    #pragma unroll
    for (int o = 1; o < 32; o <<= 1) {
        int t = __shfl_up_sync(0xFFFFFFFFu, v, o);
        if (lane >= o) v += t;
    }
    return v;
}

// phase 1: per-block sums of in-degrees
__global__ void scan1_kernel() {
    int r = blockIdx.y, b = blockIdx.x, tid = threadIdx.x;
    int i = b * SB + tid;
    int v = (i < NN) ? g_indeg[r * NN + i] : 0;
    __shared__ int ws[8];
    int lane = tid & 31, wid = tid >> 5;
    #pragma unroll
    for (int o = 16; o > 0; o >>= 1) v += __shfl_down_sync(0xFFFFFFFFu, v, o);
    if (lane == 0) ws[wid] = v;
    __syncthreads();
    if (tid == 0) {
        int s = 0;
        #pragma unroll
        for (int w = 0; w < 8; w++) s += ws[w];
        g_bsum[r][b] = s;
    }
}

// phase 2: exclusive scan of block sums (one block / relation)
__global__ void scan2_kernel() {
    int r = blockIdx.x, tid = threadIdx.x;
    int lane = tid & 31, wid = tid >> 5;
    __shared__ int ws[8];
    int v = (tid < NBLK) ? g_bsum[r][tid] : 0;
    int incl = warp_incl_scan(v, lane);
    if (lane == 31) ws[wid] = incl;
    __syncthreads();
    if (wid == 0) {
        int t = (lane < 8) ? ws[lane] : 0;
        t = warp_incl_scan(t, lane);
        if (lane < 8) ws[lane] = t;
    }
    __syncthreads();
    incl += (wid > 0) ? ws[wid - 1] : 0;
    if (tid < NBLK) g_boff[r][tid] = incl - v;
    if (tid == 255) g_rowptr[r * (NN + 1) + NN] = incl;
}

// phase 3: local exclusive scan + block offset -> rowptr, cursor
__global__ void scan3_kernel() {
    int r = blockIdx.y, b = blockIdx.x, tid = threadIdx.x;
    int lane = tid & 31, wid = tid >> 5;
    __shared__ int ws[8];
    int i = b * SB + tid;
    int v = (i < NN) ? g_indeg[r * NN + i] : 0;
    int incl = warp_incl_scan(v, lane);
    if (lane == 31) ws[wid] = incl;
    __syncthreads();
    if (wid == 0) {
        int t = (lane < 8) ? ws[lane] : 0;
        t = warp_incl_scan(t, lane);
        if (lane < 8) ws[lane] = t;
    }
    __syncthreads();
    incl += (wid > 0) ? ws[wid - 1] : 0;
    int excl = g_boff[r][b] + incl - v;
    if (i < NN) {
        g_rowptr[r * (NN + 1) + i] = excl;
        g_cursor[r * (NN + 1) + i] = excl;
    }
}

__global__ void fill_kernel(const int* __restrict__ src, const int* __restrict__ dst) {
    int i = blockIdx.x * blockDim.x + threadIdx.x;
    if (i >= RR * EE) return;
    int r = i / EE;
    int d = dst[i];
    int s = src[i];
    int pos = atomicAdd(&g_cursor[r * (NN + 1) + d], 1);
    g_cols[(size_t)r * EE + pos] = s;
    g_wts [(size_t)r * EE + pos] = g_rout[r * NN + s];
}

// ---------------- SpMM: one warp per (relation, dst-row), fp16 gather ----------------
// z[n][r*128 + c] = rin[r][n] * sum_e wts[e] * h[cols[e]][c]
__global__ void spmm_kernel(int in_sel) {
    int gw   = (blockIdx.x * blockDim.x + threadIdx.x) >> 5;
    int lane = threadIdx.x & 31;
    if (gw >= RR * NN) return;
    int r = gw / NN;
    int n = gw - r * NN;

    const __half* hin = (in_sel < 0) ? g_xh : g_hh[in_sel];
    const uint2* h2 = (const uint2*)hin;              // 4 halves / uint2, 32 per row
    const int*   cols = g_cols + (size_t)r * EE;
    const float* wts  = g_wts  + (size_t)r * EE;

    int start = g_rowptr[r * (NN + 1) + n];
    int end   = g_rowptr[r * (NN + 1) + n + 1];

    float4 acc = make_float4(0.f, 0.f, 0.f, 0.f);
    int e = start;
    #pragma unroll 1
    for (; e + 4 <= end; e += 4) {
        int s0 = cols[e], s1 = cols[e + 1], s2 = cols[e + 2], s3 = cols[e + 3];
        float w0 = wts[e], w1 = wts[e + 1], w2 = wts[e + 2], w3 = wts[e + 3];
        uint2 u0 = h2[(size_t)s0 * 32 + lane];
        uint2 u1 = h2[(size_t)s1 * 32 + lane];
        uint2 u2 = h2[(size_t)s2 * 32 + lane];
        uint2 u3 = h2[(size_t)s3 * 32 + lane];
        float2 a0 = __half22float2(*(__half2*)&u0.x), b0 = __half22float2(*(__half2*)&u0.y);
        float2 a1 = __half22float2(*(__half2*)&u1.x), b1 = __half22float2(*(__half2*)&u1.y);
        float2 a2 = __half22float2(*(__half2*)&u2.x), b2 = __half22float2(*(__half2*)&u2.y);
        float2 a3 = __half22float2(*(__half2*)&u3.x), b3 = __half22float2(*(__half2*)&u3.y);
        acc.x = fmaf(w0, a0.x, acc.x); acc.y = fmaf(w0, a0.y, acc.y);
        acc.z = fmaf(w0, b0.x, acc.z); acc.w = fmaf(w0, b0.y, acc.w);
        acc.x = fmaf(w1, a1.x, acc.x); acc.y = fmaf(w1, a1.y, acc.y);
        acc.z = fmaf(w1, b1.x, acc.z); acc.w = fmaf(w1, b1.y, acc.w);
        acc.x = fmaf(w2, a2.x, acc.x); acc.y = fmaf(w2, a2.y, acc.y);
        acc.z = fmaf(w2, b2.x, acc.z); acc.w = fmaf(w2, b2.y, acc.w);
        acc.x = fmaf(w3, a3.x, acc.x); acc.y = fmaf(w3, a3.y, acc.y);
        acc.z = fmaf(w3, b3.x, acc.z); acc.w = fmaf(w3, b3.y, acc.w);
    }
    for (; e < end; e++) {
        int s = cols[e]; float w = wts[e];
        uint2 u = h2[(size_t)s * 32 + lane];
        float2 a = __half22float2(*(__half2*)&u.x), b = __half22float2(*(__half2*)&u.y);
        acc.x = fmaf(w, a.x, acc.x); acc.y = fmaf(w, a.y, acc.y);
        acc.z = fmaf(w, b.x, acc.z); acc.w = fmaf(w, b.y, acc.w);
    }
    float ri = g_rin[r * NN + n];
    acc.x *= ri; acc.y *= ri; acc.z *= ri; acc.w *= ri;
    ((float4*)g_z)[((size_t)n * RR + r) * 32 + lane] = acc;
}

// ---------------- SGEMM: C[M,BN] = (A[M,K] @ B[K,BN] + sum_bias) * alpha ----------------
template <int BN, int NT>
__global__ __launch_bounds__(NT)
void gemm_kernel(int a_sel, const float* __restrict__ B,
                 const float* __restrict__ bias, int biasRows,
                 int o_sel, float* __restrict__ Cext,
                 int M, int K, float alpha, int leaky) {
    const int BM = 128, BK = 16, TM = 8, TN = 8;
    const float* A = (a_sel == 2) ? g_z : g_h[a_sel];
    float*       C = (o_sel == 2) ? Cext : g_h[o_sel];
    __half*      Hh = (o_sel == 0) ? g_hh[0] : (o_sel == 1) ? g_hh[1] : nullptr;

    __shared__ float As[BK][BM + 4];
    __shared__ float Bs[BK][BN];

    int tid  = threadIdx.x;
    int trow = tid / (BN / TN);
    int tcol = tid % (BN / TN);
    int blockRow = blockIdx.x * BM;

    float acc[TM][TN];
    #pragma unroll
    for (int i = 0; i < TM; i++)
        #pragma unroll
        for (int j = 0; j < TN; j++) acc[i][j] = 0.f;

    const int AV = BM * BK / 4;
    const int BV = BK * BN / 4;

    for (int k0 = 0; k0 < K; k0 += BK) {
        #pragma unroll
        for (int i = 0; i < AV / NT; i++) {
            int v   = tid + i * NT;
            int row = v / (BK / 4);
            int kq  = v % (BK / 4);
            int gr  = blockRow + row;
            float4 val = make_float4(0.f, 0.f, 0.f, 0.f);
            if (gr < M) val = *(const float4*)(A + (size_t)gr * K + k0 + kq * 4);
            As[kq * 4 + 0][row] = val.x;
            As[kq * 4 + 1][row] = val.y;
            As[kq * 4 + 2][row] = val.z;
            As[kq * 4 + 3][row] = val.w;
        }
        #pragma unroll
        for (int i = 0; i < BV / NT; i++) {
            int v  = tid + i * NT;
            int kr = v / (BN / 4);
            int jq = v % (BN / 4);
            *(float4*)&Bs[kr][jq * 4] = *(const float4*)(B + (size_t)(k0 + kr) * BN + jq * 4);
        }
        __syncthreads();
        #pragma unroll
        for (int kk = 0; kk < BK; kk++) {
            float a[TM], b[TN];
            #pragma unroll
            for (int j = 0; j < TM; j += 4) *(float4*)&a[j] = *(const float4*)&As[kk][trow * TM + j];
            #pragma unroll
            for (int j = 0; j < TN; j += 4) *(float4*)&b[j] = *(const float4*)&Bs[kk][tcol * TN + j];
            #pragma unroll
            for (int ii = 0; ii < TM; ii++)
                #pragma unroll
                for (int jj = 0; jj < TN; jj++)
                    acc[ii][jj] = fmaf(a[ii], b[jj], acc[ii][jj]);
        }
        __syncthreads();
    }

    float bsum[TN];
    #pragma unroll
    for (int jj = 0; jj < TN; jj++) {
        int col = tcol * TN + jj;
        float s = 0.f;
        for (int rr = 0; rr < biasRows; rr++) s += bias[rr * BN + col];
        bsum[jj] = s;
    }
    #pragma unroll
    for (int ii = 0; ii < TM; ii++) {
        int gr = blockRow + trow * TM + ii;
        if (gr >= M) continue;
        float o[TN];
        #pragma unroll
        for (int jj = 0; jj < TN; jj++) {
            float v = (acc[ii][jj] + bsum[jj]) * alpha;
            if (leaky && v < 0.f) v *= 0.01f;
            o[jj] = v;
        }
        #pragma unroll
        for (int j = 0; j < TN; j += 4)
            *(float4*)(C + (size_t)gr * BN + tcol * TN + j) = *(float4*)&o[j];
        if (Hh) {
            __half hb[TN];
            #pragma unroll
            for (int jj = 0; jj < TN; jj++) hb[jj] = __float2half_rn(o[jj]);
            *(uint4*)(Hh + (size_t)gr * BN + tcol * TN) = *(uint4*)hb;
        }
    }
}

// ---------------- launcher ----------------
extern "C" void kernel_launch(void* const* d_in, const int* in_sizes, int n_in,
                              void* d_out, int out_size) {
    const float* x    = (const float*)d_in[0];
    const int*   esrc = (const int*)  d_in[1];
    const int*   edst = (const int*)  d_in[2];
    const float* W0   = (const float*)d_in[3];
    const float* b0   = (const float*)d_in[4];
    const float* Wl   = (const float*)d_in[5];
    const float* bl   = (const float*)d_in[6];
    const float* Wout = (const float*)d_in[7];
    const float* bout = (const float*)d_in[8];
    float* out = (float*)d_out;

    zero_deg_kernel<<<(RR * NN + 255) / 256, 256>>>();
    xconv_kernel<<<(NN * HIDD / 2 + 255) / 256, 256>>>(x);
    deg_kernel<<<(RR * EE + 255) / 256, 256>>>(esrc, edst);
    rsqrt_kernel<<<(RR * NN + 255) / 256, 256>>>();
    scan1_kernel<<<dim3(NBLK, RR), SB>>>();
    scan2_kernel<<<RR, 256>>>();
    scan3_kernel<<<dim3(NBLK, RR), SB>>>();
    fill_kernel<<<(RR * EE + 255) / 256, 256>>>(esrc, edst);

    const int spmm_blocks = (RR * NN * 32 + 255) / 256;
    const int gemm_blocks = (NN + 127) / 128;
    const float inv_r = 1.0f / (float)RR;

    // layer 0: x -> h[0], leaky
    spmm_kernel<<<spmm_blocks, 256>>>(-1);
    gemm_kernel<128, 256><<<gemm_blocks, 256>>>(2, W0, b0, RR, 0, nullptr,
                                                NN, RR * HIDD, inv_r, 1);
    // layers 1..4
    int cur = 0;
    for (int l = 0; l < 4; l++) {
        spmm_kernel<<<spmm_blocks, 256>>>(cur);
        gemm_kernel<128, 256><<<gemm_blocks, 256>>>(
            2, Wl + (size_t)l * RR * HIDD * HIDD, bl + (size_t)l * RR * HIDD, RR,
            cur ^ 1, nullptr, NN, RR * HIDD, inv_r, (l != 3) ? 1 : 0);
        cur ^= 1;
    }
    // final linear
    gemm_kernel<64, 128><<<gemm_blocks, 128>>>(cur, Wout, bout, 1, 2, out,
                                               NN, HIDD, 1.0f, 0);
}

// round 4
// speedup vs baseline: 1.5510x; 1.4953x over previous
#include <cuda_runtime.h>
#include <cuda_fp16.h>
#include <cstddef>
#include <cstdint>

#define NN   50000
#define RR   3
#define EE   800000
#define HIDD 128
#define SB   256
#define NBLK ((NN + SB - 1) / SB)   // 196

// ---------------- static scratch (no cudaMalloc allowed) ----------------
__device__ int    g_outdeg[RR * NN];
__device__ int    g_indeg [RR * NN];
__device__ float  g_rout  [RR * NN];
__device__ float  g_rin   [RR * NN];
__device__ int    g_rowptr[RR * (NN + 1)];
__device__ int    g_cursor[RR * (NN + 1)];
__device__ int    g_bsum  [RR][NBLK];
__device__ int    g_boff  [RR][NBLK];
__device__ int    g_cols  [RR * EE];
__device__ float  g_wts   [RR * EE];
__device__ float  g_z     [(size_t)NN * RR * HIDD];   // [n][r*128+c]
__device__ float  g_h     [2][(size_t)NN * HIDD];     // fp32 (GEMM A operand)
__device__ __half g_hh    [2][(size_t)NN * HIDD];     // fp16 mirror (SpMM gather)
__device__ __half g_xh    [(size_t)NN * HIDD];        // fp16 copy of x

// ---------------- preprocessing ----------------
__global__ void zero_deg_kernel() {
    int i = blockIdx.x * blockDim.x + threadIdx.x;
    if (i < RR * NN) { g_outdeg[i] = 0; g_indeg[i] = 0; }
}

__global__ void deg_kernel(const int* __restrict__ src, const int* __restrict__ dst) {
    int i = blockIdx.x * blockDim.x + threadIdx.x;
    if (i >= RR * EE) return;
    int r = i / EE;
    atomicAdd(&g_outdeg[r * NN + src[i]], 1);
    atomicAdd(&g_indeg [r * NN + dst[i]], 1);
}

__global__ void rsqrt_kernel() {
    int i = blockIdx.x * blockDim.x + threadIdx.x;
    if (i >= RR * NN) return;
    g_rout[i] = rsqrtf(fmaxf((float)g_outdeg[i], 1.0f));
    g_rin [i] = rsqrtf(fmaxf((float)g_indeg [i], 1.0f));
}

__global__ void xconv_kernel(const float* __restrict__ x) {
    int i = blockIdx.x * blockDim.x + threadIdx.x;
    if (i < NN * HIDD / 2) {
        float2 v = ((const float2*)x)[i];
        ((__half2*)g_xh)[i] = __floats2half2_rn(v.x, v.y);
    }
}

__device__ __forceinline__ int warp_incl_scan(int v, int lane) {
    #pragma unroll
    for (int o = 1; o < 32; o <<= 1) {
        int t = __shfl_up_sync(0xFFFFFFFFu, v, o);
        if (lane >= o) v += t;
    }
    return v;
}

__global__ void scan1_kernel() {
    int r = blockIdx.y, b = blockIdx.x, tid = threadIdx.x;
    int i = b * SB + tid;
    int v = (i < NN) ? g_indeg[r * NN + i] : 0;
    __shared__ int ws[8];
    int lane = tid & 31, wid = tid >> 5;
    #pragma unroll
    for (int o = 16; o > 0; o >>= 1) v += __shfl_down_sync(0xFFFFFFFFu, v, o);
    if (lane == 0) ws[wid] = v;
    __syncthreads();
    if (tid == 0) {
        int s = 0;
        #pragma unroll
        for (int w = 0; w < 8; w++) s += ws[w];
        g_bsum[r][b] = s;
    }
}

__global__ void scan2_kernel() {
    int r = blockIdx.x, tid = threadIdx.x;
    int lane = tid & 31, wid = tid >> 5;
    __shared__ int ws[8];
    int v = (tid < NBLK) ? g_bsum[r][tid] : 0;
    int incl = warp_incl_scan(v, lane);
    if (lane == 31) ws[wid] = incl;
    __syncthreads();
    if (wid == 0) {
        int t = (lane < 8) ? ws[lane] : 0;
        t = warp_incl_scan(t, lane);
        if (lane < 8) ws[lane] = t;
    }
    __syncthreads();
    incl += (wid > 0) ? ws[wid - 1] : 0;
    if (tid < NBLK) g_boff[r][tid] = incl - v;
    if (tid == 255) g_rowptr[r * (NN + 1) + NN] = incl;
}

__global__ void scan3_kernel() {
    int r = blockIdx.y, b = blockIdx.x, tid = threadIdx.x;
    int lane = tid & 31, wid = tid >> 5;
    __shared__ int ws[8];
    int i = b * SB + tid;
    int v = (i < NN) ? g_indeg[r * NN + i] : 0;
    int incl = warp_incl_scan(v, lane);
    if (lane == 31) ws[wid] = incl;
    __syncthreads();
    if (wid == 0) {
        int t = (lane < 8) ? ws[lane] : 0;
        t = warp_incl_scan(t, lane);
        if (lane < 8) ws[lane] = t;
    }
    __syncthreads();
    incl += (wid > 0) ? ws[wid - 1] : 0;
    int excl = g_boff[r][b] + incl - v;
    if (i < NN) {
        g_rowptr[r * (NN + 1) + i] = excl;
        g_cursor[r * (NN + 1) + i] = excl;
    }
}

__global__ void fill_kernel(const int* __restrict__ src, const int* __restrict__ dst) {
    int i = blockIdx.x * blockDim.x + threadIdx.x;
    if (i >= RR * EE) return;
    int r = i / EE;
    int d = dst[i];
    int s = src[i];
    int pos = atomicAdd(&g_cursor[r * (NN + 1) + d], 1);
    g_cols[(size_t)r * EE + pos] = s;
    g_wts [(size_t)r * EE + pos] = g_rout[r * NN + s];
}

// ---------------- SpMM: one warp per (relation, dst-row), fp16 gather ----------------
__global__ void spmm_kernel(int in_sel) {
    int gw   = (blockIdx.x * blockDim.x + threadIdx.x) >> 5;
    int lane = threadIdx.x & 31;
    if (gw >= RR * NN) return;
    int r = gw / NN;
    int n = gw - r * NN;

    const __half* hin = (in_sel < 0) ? g_xh : g_hh[in_sel];
    const uint2* h2 = (const uint2*)hin;
    const int*   cols = g_cols + (size_t)r * EE;
    const float* wts  = g_wts  + (size_t)r * EE;

    int start = g_rowptr[r * (NN + 1) + n];
    int end   = g_rowptr[r * (NN + 1) + n + 1];

    float4 acc = make_float4(0.f, 0.f, 0.f, 0.f);
    int e = start;
    #pragma unroll 1
    for (; e + 4 <= end; e += 4) {
        int s0 = cols[e], s1 = cols[e + 1], s2 = cols[e + 2], s3 = cols[e + 3];
        float w0 = wts[e], w1 = wts[e + 1], w2 = wts[e + 2], w3 = wts[e + 3];
        uint2 u0 = h2[(size_t)s0 * 32 + lane];
        uint2 u1 = h2[(size_t)s1 * 32 + lane];
        uint2 u2 = h2[(size_t)s2 * 32 + lane];
        uint2 u3 = h2[(size_t)s3 * 32 + lane];
        float2 a0 = __half22float2(*(__half2*)&u0.x), b0 = __half22float2(*(__half2*)&u0.y);
        float2 a1 = __half22float2(*(__half2*)&u1.x), b1 = __half22float2(*(__half2*)&u1.y);
        float2 a2 = __half22float2(*(__half2*)&u2.x), b2 = __half22float2(*(__half2*)&u2.y);
        float2 a3 = __half22float2(*(__half2*)&u3.x), b3 = __half22float2(*(__half2*)&u3.y);
        acc.x = fmaf(w0, a0.x, acc.x); acc.y = fmaf(w0, a0.y, acc.y);
        acc.z = fmaf(w0, b0.x, acc.z); acc.w = fmaf(w0, b0.y, acc.w);
        acc.x = fmaf(w1, a1.x, acc.x); acc.y = fmaf(w1, a1.y, acc.y);
        acc.z = fmaf(w1, b1.x, acc.z); acc.w = fmaf(w1, b1.y, acc.w);
        acc.x = fmaf(w2, a2.x, acc.x); acc.y = fmaf(w2, a2.y, acc.y);
        acc.z = fmaf(w2, b2.x, acc.z); acc.w = fmaf(w2, b2.y, acc.w);
        acc.x = fmaf(w3, a3.x, acc.x); acc.y = fmaf(w3, a3.y, acc.y);
        acc.z = fmaf(w3, b3.x, acc.z); acc.w = fmaf(w3, b3.y, acc.w);
    }
    for (; e < end; e++) {
        int s = cols[e]; float w = wts[e];
        uint2 u = h2[(size_t)s * 32 + lane];
        float2 a = __half22float2(*(__half2*)&u.x), b = __half22float2(*(__half2*)&u.y);
        acc.x = fmaf(w, a.x, acc.x); acc.y = fmaf(w, a.y, acc.y);
        acc.z = fmaf(w, b.x, acc.z); acc.w = fmaf(w, b.y, acc.w);
    }
    float ri = g_rin[r * NN + n];
    acc.x *= ri; acc.y *= ri; acc.z *= ri; acc.w *= ri;
    ((float4*)g_z)[((size_t)n * RR + r) * 32 + lane] = acc;
}

// ---------------- tf32 tensor-core GEMM ----------------
__device__ __forceinline__ uint32_t f2tf32(float f) {
    uint32_t r;
    asm("cvt.rna.tf32.f32 %0, %1;" : "=r"(r) : "f"(f));
    return r;
}

__device__ __forceinline__ void mma_tf32(float* c, const uint32_t* a,
                                         uint32_t b0, uint32_t b1) {
    asm volatile(
        "mma.sync.aligned.m16n8k8.row.col.f32.tf32.tf32.f32 "
        "{%0,%1,%2,%3}, {%4,%5,%6,%7}, {%8,%9}, {%0,%1,%2,%3};"
        : "+f"(c[0]), "+f"(c[1]), "+f"(c[2]), "+f"(c[3])
        : "r"(a[0]), "r"(a[1]), "r"(a[2]), "r"(a[3]), "r"(b0), "r"(b1));
}

// C[M,BN] = (A[M,K] @ B[K,BN] + sum_rows(bias)) * alpha,  optional leaky, fp16 mirror.
// BM=128 fixed. Warps: 2 (m) x WN (n). Each warp: 64 rows x 32 cols = 4x4 m16n8 tiles.
template <int BN, int WN, int NT>
__global__ __launch_bounds__(NT)
void gemm_tc_kernel(int a_sel, const float* __restrict__ Bmat,
                    const float* __restrict__ bias, int biasRows,
                    int o_sel, float* __restrict__ Cext,
                    int M, int K, float alpha, int leaky) {
    const int BM = 128, BK = 32;
    const float* A = (a_sel == 2) ? g_z : g_h[a_sel];
    float*       C = (o_sel == 2) ? Cext : g_h[o_sel];
    __half*      Hh = (o_sel == 0) ? g_hh[0] : (o_sel == 1) ? g_hh[1] : nullptr;

    __shared__ uint32_t As[BM][BK + 4];      // row stride 36 words (144B, 16B-aligned)
    __shared__ uint32_t Bs[BK][BN + 4];      // row stride BN+4 words

    int tid  = threadIdx.x;
    int wid  = tid >> 5;
    int lane = tid & 31;
    int g    = lane >> 2;       // groupID
    int tg   = lane & 3;        // thread-in-group
    int wm   = wid / WN;        // 0..1
    int wn   = wid % WN;        // 0..WN-1
    int blockRow = blockIdx.x * BM;

    float acc[4][4][4];         // [m-tile][n-tile][c-reg]
    #pragma unroll
    for (int i = 0; i < 4; i++)
        #pragma unroll
        for (int j = 0; j < 4; j++)
            #pragma unroll
            for (int q = 0; q < 4; q++) acc[i][j][q] = 0.f;

    const int ASLOT = BM * (BK / 4);   // float4 slots
    const int BSLOT = BK * (BN / 4);

    for (int k0 = 0; k0 < K; k0 += BK) {
        #pragma unroll
        for (int i = 0; i < ASLOT / NT; i++) {
            int v = tid + i * NT;
            int row = v >> 3, kq = v & 7;
            int gr = blockRow + row;
            float4 val = make_float4(0.f, 0.f, 0.f, 0.f);
            if (gr < M) val = *(const float4*)(A + (size_t)gr * K + k0 + kq * 4);
            uint4 t;
            t.x = f2tf32(val.x); t.y = f2tf32(val.y);
            t.z = f2tf32(val.z); t.w = f2tf32(val.w);
            *(uint4*)&As[row][kq * 4] = t;
        }
        #pragma unroll
        for (int i = 0; i < BSLOT / NT; i++) {
            int v = tid + i * NT;
            int kr = v / (BN / 4), jq = v % (BN / 4);
            float4 val = *(const float4*)(Bmat + (size_t)(k0 + kr) * BN + jq * 4);
            uint4 t;
            t.x = f2tf32(val.x); t.y = f2tf32(val.y);
            t.z = f2tf32(val.z); t.w = f2tf32(val.w);
            *(uint4*)&Bs[kr][jq * 4] = t;
        }
        __syncthreads();

        #pragma unroll
        for (int kk = 0; kk < BK / 8; kk++) {
            int kb = kk * 8;
            uint32_t af[4][4];
            #pragma unroll
            for (int mt = 0; mt < 4; mt++) {
                int r = wm * 64 + mt * 16 + g;
                af[mt][0] = As[r][kb + tg];
                af[mt][1] = As[r + 8][kb + tg];
                af[mt][2] = As[r][kb + tg + 4];
                af[mt][3] = As[r + 8][kb + tg + 4];
            }
            #pragma unroll
            for (int nt = 0; nt < 4; nt++) {
                int cidx = wn * 32 + nt * 8 + g;
                uint32_t b0 = Bs[kb + tg][cidx];
                uint32_t b1 = Bs[kb + tg + 4][cidx];
                #pragma unroll
                for (int mt = 0; mt < 4; mt++)
                    mma_tf32(acc[mt][nt], af[mt], b0, b1);
            }
        }
        __syncthreads();
    }

    // ---- epilogue ----
    float2 bs[4];
    #pragma unroll
    for (int nt = 0; nt < 4; nt++) {
        int col = wn * 32 + nt * 8 + tg * 2;
        float sx = 0.f, sy = 0.f;
        for (int rr = 0; rr < biasRows; rr++) {
            sx += bias[rr * BN + col];
            sy += bias[rr * BN + col + 1];
        }
        bs[nt].x = sx; bs[nt].y = sy;
    }
    #pragma unroll
    for (int mt = 0; mt < 4; mt++) {
        int r0 = blockRow + wm * 64 + mt * 16 + g;
        int r1 = r0 + 8;
        #pragma unroll
        for (int nt = 0; nt < 4; nt++) {
            int col = wn * 32 + nt * 8 + tg * 2;
            float v0 = (acc[mt][nt][0] + bs[nt].x) * alpha;
            float v1 = (acc[mt][nt][1] + bs[nt].y) * alpha;
            float v2 = (acc[mt][nt][2] + bs[nt].x) * alpha;
            float v3 = (acc[mt][nt][3] + bs[nt].y) * alpha;
            if (leaky) {
                if (v0 < 0.f) v0 *= 0.01f;
                if (v1 < 0.f) v1 *= 0.01f;
                if (v2 < 0.f) v2 *= 0.01f;
                if (v3 < 0.f) v3 *= 0.01f;
            }
            if (r0 < M) {
                *(float2*)(C + (size_t)r0 * BN + col) = make_float2(v0, v1);
                if (Hh) *(__half2*)(Hh + (size_t)r0 * BN + col) = __floats2half2_rn(v0, v1);
            }
            if (r1 < M) {
                *(float2*)(C + (size_t)r1 * BN + col) = make_float2(v2, v3);
                if (Hh) *(__half2*)(Hh + (size_t)r1 * BN + col) = __floats2half2_rn(v2, v3);
            }
        }
    }
}

// ---------------- launcher ----------------
extern "C" void kernel_launch(void* const* d_in, const int* in_sizes, int n_in,
                              void* d_out, int out_size) {
    const float* x    = (const float*)d_in[0];
    const int*   esrc = (const int*)  d_in[1];
    const int*   edst = (const int*)  d_in[2];
    const float* W0   = (const float*)d_in[3];
    const float* b0   = (const float*)d_in[4];
    const float* Wl   = (const float*)d_in[5];
    const float* bl   = (const float*)d_in[6];
    const float* Wout = (const float*)d_in[7];
    const float* bout = (const float*)d_in[8];
    float* out = (float*)d_out;

    zero_deg_kernel<<<(RR * NN + 255) / 256, 256>>>();
    xconv_kernel<<<(NN * HIDD / 2 + 255) / 256, 256>>>(x);
    deg_kernel<<<(RR * EE + 255) / 256, 256>>>(esrc, edst);
    rsqrt_kernel<<<(RR * NN + 255) / 256, 256>>>();
    scan1_kernel<<<dim3(NBLK, RR), SB>>>();
    scan2_kernel<<<RR, 256>>>();
    scan3_kernel<<<dim3(NBLK, RR), SB>>>();
    fill_kernel<<<(RR * EE + 255) / 256, 256>>>(esrc, edst);

    const int spmm_blocks = (RR * NN * 32 + 255) / 256;
    const int gemm_blocks = (NN + 127) / 128;   // 391
    const float inv_r = 1.0f / (float)RR;

    // layer 0: x -> h[0], leaky
    spmm_kernel<<<spmm_blocks, 256>>>(-1);
    gemm_tc_kernel<128, 4, 256><<<gemm_blocks, 256>>>(2, W0, b0, RR, 0, nullptr,
                                                      NN, RR * HIDD, inv_r, 1);
    // layers 1..4
    int cur = 0;
    for (int l = 0; l < 4; l++) {
        spmm_kernel<<<spmm_blocks, 256>>>(cur);
        gemm_tc_kernel<128, 4, 256><<<gemm_blocks, 256>>>(
            2, Wl + (size_t)l * RR * HIDD * HIDD, bl + (size_t)l * RR * HIDD, RR,
            cur ^ 1, nullptr, NN, RR * HIDD, inv_r, (l != 3) ? 1 : 0);
        cur ^= 1;
    }
    // final linear
    gemm_tc_kernel<64, 2, 128><<<gemm_blocks, 128>>>(cur, Wout, bout, 1, 2, out,
                                                     NN, HIDD, 1.0f, 0);
}

// round 6
// speedup vs baseline: 2.1116x; 1.3614x over previous
#include <cuda_runtime.h>
#include <cuda_fp16.h>
#include <cstddef>
#include <cstdint>

#define NN   50000
#define RR   3
#define EE   800000
#define HIDD 128
#define KK   (RR * HIDD)            // 384
#define SB   256
#define NBLK ((NN + SB - 1) / SB)   // 196

// ---------------- static scratch (no cudaMalloc allowed) ----------------
__device__ int    g_outdeg[RR * NN];
__device__ int    g_indeg [RR * NN];
__device__ float  g_rout  [RR * NN];
__device__ float  g_rin   [RR * NN];
__device__ int    g_rowptr[RR * (NN + 1)];
__device__ int    g_cursor[RR * (NN + 1)];
__device__ int    g_bsum  [RR][NBLK];
__device__ int    g_boff  [RR][NBLK];
__device__ int    g_cols  [RR * EE];
__device__ float  g_wts   [RR * EE];
__device__ __half g_zh    [(size_t)NN * KK];          // SpMM output (GEMM A), fp16
__device__ __half g_hh    [2][(size_t)NN * HIDD];     // layer activations, fp16
__device__ __half g_xh    [(size_t)NN * HIDD];        // fp16 copy of x
__device__ __half g_wt    [5][HIDD][KK];              // transposed fp16 weights [n][k]
__device__ __half g_wtout [64][HIDD];                 // transposed fp16 Wout

// ---------------- preprocessing ----------------
__global__ void zero_deg_kernel() {
    int i = blockIdx.x * blockDim.x + threadIdx.x;
    if (i < RR * NN) { g_outdeg[i] = 0; g_indeg[i] = 0; }
}

__global__ void deg_kernel(const int* __restrict__ src, const int* __restrict__ dst) {
    int i = blockIdx.x * blockDim.x + threadIdx.x;
    if (i >= RR * EE) return;
    int r = i / EE;
    atomicAdd(&g_outdeg[r * NN + src[i]], 1);
    atomicAdd(&g_indeg [r * NN + dst[i]], 1);
}

__global__ void rsqrt_kernel() {
    int i = blockIdx.x * blockDim.x + threadIdx.x;
    if (i >= RR * NN) return;
    g_rout[i] = rsqrtf(fmaxf((float)g_outdeg[i], 1.0f));
    g_rin [i] = rsqrtf(fmaxf((float)g_indeg [i], 1.0f));
}

__global__ void xconv_kernel(const float* __restrict__ x) {
    int i = blockIdx.x * blockDim.x + threadIdx.x;
    if (i < NN * HIDD / 2) {
        float2 v = ((const float2*)x)[i];
        ((__half2*)g_xh)[i] = __floats2half2_rn(v.x, v.y);
    }
}

// transpose + fp16-convert all weights: g_wt[L][n][k], g_wtout[n][k]
__global__ void wconv_kernel(const float* __restrict__ W0,
                             const float* __restrict__ Wl,
                             const float* __restrict__ Wout) {
    int i = blockIdx.x * blockDim.x + threadIdx.x;
    const int NW = 5 * HIDD * KK;
    if (i < NW) {
        int L = i / (HIDD * KK);
        int rem = i - L * (HIDD * KK);
        int n = rem / KK;
        int k = rem - n * KK;
        const float* src = (L == 0) ? W0 : (Wl + (size_t)(L - 1) * KK * HIDD);
        g_wt[L][n][k] = __float2half_rn(src[(size_t)k * HIDD + n]);
    } else if (i < NW + 64 * HIDD) {
        int j = i - NW;
        int n = j / HIDD;
        int k = j - n * HIDD;
        g_wtout[n][k] = __float2half_rn(Wout[(size_t)k * 64 + n]);
    }
}

__device__ __forceinline__ int warp_incl_scan(int v, int lane) {
    #pragma unroll
    for (int o = 1; o < 32; o <<= 1) {
        int t = __shfl_up_sync(0xFFFFFFFFu, v, o);
        if (lane >= o) v += t;
    }
    return v;
}

__global__ void scan1_kernel() {
    int r = blockIdx.y, b = blockIdx.x, tid = threadIdx.x;
    int i = b * SB + tid;
    int v = (i < NN) ? g_indeg[r * NN + i] : 0;
    __shared__ int ws[8];
    int lane = tid & 31, wid = tid >> 5;
    #pragma unroll
    for (int o = 16; o > 0; o >>= 1) v += __shfl_down_sync(0xFFFFFFFFu, v, o);
    if (lane == 0) ws[wid] = v;
    __syncthreads();
    if (tid == 0) {
        int s = 0;
        #pragma unroll
        for (int w = 0; w < 8; w++) s += ws[w];
        g_bsum[r][b] = s;
    }
}

__global__ void scan2_kernel() {
    int r = blockIdx.x, tid = threadIdx.x;
    int lane = tid & 31, wid = tid >> 5;
    __shared__ int ws[8];
    int v = (tid < NBLK) ? g_bsum[r][tid] : 0;
    int incl = warp_incl_scan(v, lane);
    if (lane == 31) ws[wid] = incl;
    __syncthreads();
    if (wid == 0) {
        int t = (lane < 8) ? ws[lane] : 0;
        t = warp_incl_scan(t, lane);
        if (lane < 8) ws[lane] = t;
    }
    __syncthreads();
    incl += (wid > 0) ? ws[wid - 1] : 0;
    if (tid < NBLK) g_boff[r][tid] = incl - v;
    if (tid == 255) g_rowptr[r * (NN + 1) + NN] = incl;
}

__global__ void scan3_kernel() {
    int r = blockIdx.y, b = blockIdx.x, tid = threadIdx.x;
    int lane = tid & 31, wid = tid >> 5;
    __shared__ int ws[8];
    int i = b * SB + tid;
    int v = (i < NN) ? g_indeg[r * NN + i] : 0;
    int incl = warp_incl_scan(v, lane);
    if (lane == 31) ws[wid] = incl;
    __syncthreads();
    if (wid == 0) {
        int t = (lane < 8) ? ws[lane] : 0;
        t = warp_incl_scan(t, lane);
        if (lane < 8) ws[lane] = t;
    }
    __syncthreads();
    incl += (wid > 0) ? ws[wid - 1] : 0;
    int excl = g_boff[r][b] + incl - v;
    if (i < NN) {
        g_rowptr[r * (NN + 1) + i] = excl;
        g_cursor[r * (NN + 1) + i] = excl;
    }
}

__global__ void fill_kernel(const int* __restrict__ src, const int* __restrict__ dst) {
    int i = blockIdx.x * blockDim.x + threadIdx.x;
    if (i >= RR * EE) return;
    int r = i / EE;
    int d = dst[i];
    int s = src[i];
    int pos = atomicAdd(&g_cursor[r * (NN + 1) + d], 1);
    g_cols[(size_t)r * EE + pos] = s;
    g_wts [(size_t)r * EE + pos] = g_rout[r * NN + s];
}

// ---------------- SpMM: one warp per (relation, dst-row), fp16 gather -> fp16 z ----------------
__global__ void spmm_kernel(int in_sel) {
    int gw   = (blockIdx.x * blockDim.x + threadIdx.x) >> 5;
    int lane = threadIdx.x & 31;
    if (gw >= RR * NN) return;
    int r = gw / NN;
    int n = gw - r * NN;

    const __half* hin = (in_sel < 0) ? g_xh : g_hh[in_sel];
    const uint2* h2 = (const uint2*)hin;
    const int*   cols = g_cols + (size_t)r * EE;
    const float* wts  = g_wts  + (size_t)r * EE;

    int start = g_rowptr[r * (NN + 1) + n];
    int end   = g_rowptr[r * (NN + 1) + n + 1];

    float4 acc = make_float4(0.f, 0.f, 0.f, 0.f);
    int e = start;
    #pragma unroll 1
    for (; e + 4 <= end; e += 4) {
        int s0 = cols[e], s1 = cols[e + 1], s2 = cols[e + 2], s3 = cols[e + 3];
        float w0 = wts[e], w1 = wts[e + 1], w2 = wts[e + 2], w3 = wts[e + 3];
        uint2 u0 = h2[(size_t)s0 * 32 + lane];
        uint2 u1 = h2[(size_t)s1 * 32 + lane];
        uint2 u2 = h2[(size_t)s2 * 32 + lane];
        uint2 u3 = h2[(size_t)s3 * 32 + lane];
        float2 a0 = __half22float2(*(__half2*)&u0.x), b0 = __half22float2(*(__half2*)&u0.y);
        float2 a1 = __half22float2(*(__half2*)&u1.x), b1 = __half22float2(*(__half2*)&u1.y);
        float2 a2 = __half22float2(*(__half2*)&u2.x), b2 = __half22float2(*(__half2*)&u2.y);
        float2 a3 = __half22float2(*(__half2*)&u3.x), b3 = __half22float2(*(__half2*)&u3.y);
        acc.x = fmaf(w0, a0.x, acc.x); acc.y = fmaf(w0, a0.y, acc.y);
        acc.z = fmaf(w0, b0.x, acc.z); acc.w = fmaf(w0, b0.y, acc.w);
        acc.x = fmaf(w1, a1.x, acc.x); acc.y = fmaf(w1, a1.y, acc.y);
        acc.z = fmaf(w1, b1.x, acc.z); acc.w = fmaf(w1, b1.y, acc.w);
        acc.x = fmaf(w2, a2.x, acc.x); acc.y = fmaf(w2, a2.y, acc.y);
        acc.z = fmaf(w2, b2.x, acc.z); acc.w = fmaf(w2, b2.y, acc.w);
        acc.x = fmaf(w3, a3.x, acc.x); acc.y = fmaf(w3, a3.y, acc.y);
        acc.z = fmaf(w3, b3.x, acc.z); acc.w = fmaf(w3, b3.y, acc.w);
    }
    for (; e < end; e++) {
        int s = cols[e]; float w = wts[e];
        uint2 u = h2[(size_t)s * 32 + lane];
        float2 a = __half22float2(*(__half2*)&u.x), b = __half22float2(*(__half2*)&u.y);
        acc.x = fmaf(w, a.x, acc.x); acc.y = fmaf(w, a.y, acc.y);
        acc.z = fmaf(w, b.x, acc.z); acc.w = fmaf(w, b.y, acc.w);
    }
    float ri = g_rin[r * NN + n];
    uint2 o;
    *(__half2*)&o.x = __floats2half2_rn(acc.x * ri, acc.y * ri);
    *(__half2*)&o.y = __floats2half2_rn(acc.z * ri, acc.w * ri);
    ((uint2*)g_zh)[((size_t)n * RR + r) * 32 + lane] = o;
}

// ---------------- fp16 tensor-core GEMM (m16n8k16, fp32 accumulate) ----------------
__device__ __forceinline__ void mma_f16(float* c, const uint32_t* a,
                                        uint32_t b0, uint32_t b1) {
    asm volatile(
        "mma.sync.aligned.m16n8k16.row.col.f32.f16.f16.f32 "
        "{%0,%1,%2,%3}, {%4,%5,%6,%7}, {%8,%9}, {%0,%1,%2,%3};"
        : "+f"(c[0]), "+f"(c[1]), "+f"(c[2]), "+f"(c[3])
        : "r"(a[0]), "r"(a[1]), "r"(a[2]), "r"(a[3]), "r"(b0), "r"(b1));
}

// C[M,BN] = (A[M,K] @ Wt^T + sum_rows(bias)) * alpha.
// a_sel: -1 -> g_zh (K=KK), 0/1 -> g_hh[a_sel] (K=HIDD).
// wsel:  0..4 -> g_wt[wsel], 5 -> g_wtout.
// o_sel: 0/1 -> g_hh[o_sel] (fp16), 2 -> Cext (fp32).
template <int BN, int WN, int NT>
__global__ __launch_bounds__(NT)
void gemm_tc_kernel(int a_sel, int wsel,
                    const float* __restrict__ bias, int biasRows,
                    int o_sel, float* __restrict__ Cext,
                    int M, int K, float alpha, int leaky) {
    const int BM = 128, BK = 64, PAD = 8;
    const __half* A  = (a_sel < 0) ? g_zh : g_hh[a_sel];
    const __half* Wt = (wsel < 5) ? &g_wt[wsel][0][0] : &g_wtout[0][0];
    __half* Hout = (o_sel == 2) ? nullptr : g_hh[o_sel];

    __shared__ __half As[BM][BK + PAD];     // stride 72 halves = 36 words
    __shared__ __half Bs[BN][BK + PAD];

    int tid  = threadIdx.x;
    int wid  = tid >> 5;
    int lane = tid & 31;
    int g    = lane >> 2;
    int tg   = lane & 3;
    int wm   = wid / WN;
    int wn   = wid % WN;
    int blockRow = blockIdx.x * BM;

    float acc[4][4][4];
    #pragma unroll
    for (int i = 0; i < 4; i++)
        #pragma unroll
        for (int j = 0; j < 4; j++)
            #pragma unroll
            for (int q = 0; q < 4; q++) acc[i][j][q] = 0.f;

    const int ASLOT = BM * (BK / 8);   // uint4 (8-half) slots
    const int BSLOT = BN * (BK / 8);

    for (int k0 = 0; k0 < K; k0 += BK) {
        #pragma unroll
        for (int i = 0; i < ASLOT / NT; i++) {
            int v = tid + i * NT;
            int row = v >> 3, kq = v & 7;
            int gr = blockRow + row;
            uint4 val = make_uint4(0, 0, 0, 0);
            if (gr < M) val = *(const uint4*)(A + (size_t)gr * K + k0 + kq * 8);
            *(uint4*)&As[row][kq * 8] = val;
        }
        #pragma unroll
        for (int i = 0; i < BSLOT / NT; i++) {
            int v = tid + i * NT;
            int n = v >> 3, kq = v & 7;
            *(uint4*)&Bs[n][kq * 8] = *(const uint4*)(Wt + (size_t)n * K + k0 + kq * 8);
        }
        __syncthreads();

        #pragma unroll
        for (int kk = 0; kk < BK / 16; kk++) {
            int kb = kk * 16;
            uint32_t af[4][4];
            #pragma unroll
            for (int mt = 0; mt < 4; mt++) {
                int r = wm * 64 + mt * 16 + g;
                af[mt][0] = *(const uint32_t*)&As[r][kb + tg * 2];
                af[mt][1] = *(const uint32_t*)&As[r + 8][kb + tg * 2];
                af[mt][2] = *(const uint32_t*)&As[r][kb + tg * 2 + 8];
                af[mt][3] = *(const uint32_t*)&As[r + 8][kb + tg * 2 + 8];
            }
            #pragma unroll
            for (int nt = 0; nt < 4; nt++) {
                int cidx = wn * 32 + nt * 8 + g;
                uint32_t b0 = *(const uint32_t*)&Bs[cidx][kb + tg * 2];
                uint32_t b1 = *(const uint32_t*)&Bs[cidx][kb + tg * 2 + 8];
                #pragma unroll
                for (int mt = 0; mt < 4; mt++)
                    mma_f16(acc[mt][nt], af[mt], b0, b1);
            }
        }
        __syncthreads();
    }

    // ---- epilogue ----
    float2 bs[4];
    #pragma unroll
    for (int nt = 0; nt < 4; nt++) {
        int col = wn * 32 + nt * 8 + tg * 2;
        float sx = 0.f, sy = 0.f;
        for (int rr = 0; rr < biasRows; rr++) {
            sx += bias[rr * BN + col];
            sy += bias[rr * BN + col + 1];
        }
        bs[nt].x = sx; bs[nt].y = sy;
    }
    #pragma unroll
    for (int mt = 0; mt < 4; mt++) {
        int r0 = blockRow + wm * 64 + mt * 16 + g;
        int r1 = r0 + 8;
        #pragma unroll
        for (int nt = 0; nt < 4; nt++) {
            int col = wn * 32 + nt * 8 + tg * 2;
            float v0 = (acc[mt][nt][0] + bs[nt].x) * alpha;
            float v1 = (acc[mt][nt][1] + bs[nt].y) * alpha;
            float v2 = (acc[mt][nt][2] + bs[nt].x) * alpha;
            float v3 = (acc[mt][nt][3] + bs[nt].y) * alpha;
            if (leaky) {
                if (v0 < 0.f) v0 *= 0.01f;
                if (v1 < 0.f) v1 *= 0.01f;
                if (v2 < 0.f) v2 *= 0.01f;
                if (v3 < 0.f) v3 *= 0.01f;
            }
            if (o_sel == 2) {
                if (r0 < M) *(float2*)(Cext + (size_t)r0 * BN + col) = make_float2(v0, v1);
                if (r1 < M) *(float2*)(Cext + (size_t)r1 * BN + col) = make_float2(v2, v3);
            } else {
                if (r0 < M) *(__half2*)(Hout + (size_t)r0 * BN + col) = __floats2half2_rn(v0, v1);
                if (r1 < M) *(__half2*)(Hout + (size_t)r1 * BN + col) = __floats2half2_rn(v2, v3);
            }
        }
    }
}

// ---------------- launcher ----------------
extern "C" void kernel_launch(void* const* d_in, const int* in_sizes, int n_in,
                              void* d_out, int out_size) {
    const float* x    = (const float*)d_in[0];
    const int*   esrc = (const int*)  d_in[1];
    const int*   edst = (const int*)  d_in[2];
    const float* W0   = (const float*)d_in[3];
    const float* b0   = (const float*)d_in[4];
    const float* Wl   = (const float*)d_in[5];
    const float* bl   = (const float*)d_in[6];
    const float* Wout = (const float*)d_in[7];
    const float* bout = (const float*)d_in[8];
    float* out = (float*)d_out;

    zero_deg_kernel<<<(RR * NN + 255) / 256, 256>>>();
    xconv_kernel<<<(NN * HIDD / 2 + 255) / 256, 256>>>(x);
    wconv_kernel<<<(5 * HIDD * KK + 64 * HIDD + 255) / 256, 256>>>(W0, Wl, Wout);
    deg_kernel<<<(RR * EE + 255) / 256, 256>>>(esrc, edst);
    rsqrt_kernel<<<(RR * NN + 255) / 256, 256>>>();
    scan1_kernel<<<dim3(NBLK, RR), SB>>>();
    scan2_kernel<<<RR, 256>>>();
    scan3_kernel<<<dim3(NBLK, RR), SB>>>();
    fill_kernel<<<(RR * EE + 255) / 256, 256>>>(esrc, edst);

    const int spmm_blocks = (RR * NN * 32 + 255) / 256;
    const int gemm_blocks = (NN + 127) / 128;   // 391
    const float inv_r = 1.0f / (float)RR;

    // layer 0: x -> h[0], leaky
    spmm_kernel<<<spmm_blocks, 256>>>(-1);
    gemm_tc_kernel<128, 4, 256><<<gemm_blocks, 256>>>(
        -1, 0, b0, RR, 0, nullptr, NN, KK, inv_r, 1);
    // layers 1..4
    int cur = 0;
    for (int l = 0; l < 4; l++) {
        spmm_kernel<<<spmm_blocks, 256>>>(cur);
        gemm_tc_kernel<128, 4, 256><<<gemm_blocks, 256>>>(
            -1, l + 1, bl + (size_t)l * RR * HIDD, RR,
            cur ^ 1, nullptr, NN, KK, inv_r, (l != 3) ? 1 : 0);
        cur ^= 1;
    }
    // final linear (fp32 out)
    gemm_tc_kernel<64, 2, 128><<<gemm_blocks, 128>>>(
        cur, 5, bout, 1, 2, out, NN, HIDD, 1.0f, 0);
}

// round 9
// speedup vs baseline: 2.1896x; 1.0369x over previous
#include <cuda_runtime.h>
#include <cuda_fp16.h>
#include <cstddef>
#include <cstdint>

#define NN   50000
#define RR   3
#define EE   800000
#define HIDD 128
#define KK   (RR * HIDD)            // 384
#define SB   256
#define NBLK ((NN + SB - 1) / SB)   // 196

// ---------------- static scratch (no cudaMalloc allowed) ----------------
__device__ int    g_outdeg[RR * NN];
__device__ int    g_indeg [RR * NN];
__device__ float  g_rout  [RR * NN];
__device__ float  g_rin   [RR * NN];
__device__ int    g_rowptr[RR * (NN + 1)];
__device__ int    g_cursor[RR * (NN + 1)];
__device__ int    g_bsum  [RR][NBLK];
__device__ int    g_boff  [RR][NBLK];
__device__ int2   g_edge  [RR * EE];                  // (src col, weight bits)
__device__ __half g_zh    [(size_t)NN * KK];          // SpMM output (GEMM A), fp16
__device__ __half g_hh    [2][(size_t)NN * HIDD];     // layer activations, fp16
__device__ __half g_xh    [(size_t)NN * HIDD];        // fp16 copy of x
__device__ __half g_wt    [5][HIDD][KK];              // transposed fp16 weights [n][k]
__device__ __half g_wtout [64][HIDD];                 // transposed fp16 Wout

// ---------------- preprocessing ----------------
__global__ void zero_deg_kernel() {
    int i = blockIdx.x * blockDim.x + threadIdx.x;
    if (i < RR * NN) { g_outdeg[i] = 0; g_indeg[i] = 0; }
}

__global__ void deg_kernel(const int* __restrict__ src, const int* __restrict__ dst) {
    int i = blockIdx.x * blockDim.x + threadIdx.x;
    if (i >= RR * EE) return;
    int r = i / EE;
    atomicAdd(&g_outdeg[r * NN + src[i]], 1);
    atomicAdd(&g_indeg [r * NN + dst[i]], 1);
}

__global__ void rsqrt_kernel() {
    int i = blockIdx.x * blockDim.x + threadIdx.x;
    if (i >= RR * NN) return;
    g_rout[i] = rsqrtf(fmaxf((float)g_outdeg[i], 1.0f));
    g_rin [i] = rsqrtf(fmaxf((float)g_indeg [i], 1.0f));
}

__global__ void xconv_kernel(const float* __restrict__ x) {
    int i = blockIdx.x * blockDim.x + threadIdx.x;
    if (i < NN * HIDD / 2) {
        float2 v = ((const float2*)x)[i];
        ((__half2*)g_xh)[i] = __floats2half2_rn(v.x, v.y);
    }
}

// transpose + fp16-convert all weights
__global__ void wconv_kernel(const float* __restrict__ W0,
                             const float* __restrict__ Wl,
                             const float* __restrict__ Wout) {
    int i = blockIdx.x * blockDim.x + threadIdx.x;
    const int NW = 5 * HIDD * KK;
    if (i < NW) {
        int L = i / (HIDD * KK);
        int rem = i - L * (HIDD * KK);
        int n = rem / KK;
        int k = rem - n * KK;
        const float* src = (L == 0) ? W0 : (Wl + (size_t)(L - 1) * KK * HIDD);
        g_wt[L][n][k] = __float2half_rn(src[(size_t)k * HIDD + n]);
    } else if (i < NW + 64 * HIDD) {
        int j = i - NW;
        int n = j / HIDD;
        int k = j - n * HIDD;
        g_wtout[n][k] = __float2half_rn(Wout[(size_t)k * 64 + n]);
    }
}

__device__ __forceinline__ int warp_incl_scan(int v, int lane) {
    #pragma unroll
    for (int o = 1; o < 32; o <<= 1) {
        int t = __shfl_up_sync(0xFFFFFFFFu, v, o);
        if (lane >= o) v += t;
    }
    return v;
}

__global__ void scan1_kernel() {
    int r = blockIdx.y, b = blockIdx.x, tid = threadIdx.x;
    int i = b * SB + tid;
    int v = (i < NN) ? g_indeg[r * NN + i] : 0;
    __shared__ int ws[8];
    int lane = tid & 31, wid = tid >> 5;
    #pragma unroll
    for (int o = 16; o > 0; o >>= 1) v += __shfl_down_sync(0xFFFFFFFFu, v, o);
    if (lane == 0) ws[wid] = v;
    __syncthreads();
    if (tid == 0) {
        int s = 0;
        #pragma unroll
        for (int w = 0; w < 8; w++) s += ws[w];
        g_bsum[r][b] = s;
    }
}

__global__ void scan2_kernel() {
    int r = blockIdx.x, tid = threadIdx.x;
    int lane = tid & 31, wid = tid >> 5;
    __shared__ int ws[8];
    int v = (tid < NBLK) ? g_bsum[r][tid] : 0;
    int incl = warp_incl_scan(v, lane);
    if (lane == 31) ws[wid] = incl;
    __syncthreads();
    if (wid == 0) {
        int t = (lane < 8) ? ws[lane] : 0;
        t = warp_incl_scan(t, lane);
        if (lane < 8) ws[lane] = t;
    }
    __syncthreads();
    incl += (wid > 0) ? ws[wid - 1] : 0;
    if (tid < NBLK) g_boff[r][tid] = incl - v;
    if (tid == 255) g_rowptr[r * (NN + 1) + NN] = incl;
}

__global__ void scan3_kernel() {
    int r = blockIdx.y, b = blockIdx.x, tid = threadIdx.x;
    int lane = tid & 31, wid = tid >> 5;
    __shared__ int ws[8];
    int i = b * SB + tid;
    int v = (i < NN) ? g_indeg[r * NN + i] : 0;
    int incl = warp_incl_scan(v, lane);
    if (lane == 31) ws[wid] = incl;
    __syncthreads();
    if (wid == 0) {
        int t = (lane < 8) ? ws[lane] : 0;
        t = warp_incl_scan(t, lane);
        if (lane < 8) ws[lane] = t;
    }
    __syncthreads();
    incl += (wid > 0) ? ws[wid - 1] : 0;
    int excl = g_boff[r][b] + incl - v;
    if (i < NN) {
        g_rowptr[r * (NN + 1) + i] = excl;
        g_cursor[r * (NN + 1) + i] = excl;
    }
}

__global__ void fill_kernel(const int* __restrict__ src, const int* __restrict__ dst) {
    int i = blockIdx.x * blockDim.x + threadIdx.x;
    if (i >= RR * EE) return;
    int r = i / EE;
    int d = dst[i];
    int s = src[i];
    int pos = atomicAdd(&g_cursor[r * (NN + 1) + d], 1);
    g_edge[(size_t)r * EE + pos] = make_int2(s, __float_as_int(g_rout[r * NN + s]));
}

// ---------------- SpMM: one warp per (relation, dst-row), MLP-8 fp16 gather ----------------
__global__ void spmm_kernel(int in_sel) {
    int gw   = (blockIdx.x * blockDim.x + threadIdx.x) >> 5;
    int lane = threadIdx.x & 31;
    if (gw >= RR * NN) return;
    int r = gw / NN;
    int n = gw - r * NN;

    const __half* hin = (in_sel < 0) ? g_xh : g_hh[in_sel];
    const uint2* h2 = (const uint2*)hin;
    const int2* edges = g_edge + (size_t)r * EE;

    int start = g_rowptr[r * (NN + 1) + n];
    int end   = g_rowptr[r * (NN + 1) + n + 1];

    float4 acc = make_float4(0.f, 0.f, 0.f, 0.f);
    int e = start;
    #pragma unroll 1
    for (; e + 8 <= end; e += 8) {
        int2 ed[8];
        #pragma unroll
        for (int j = 0; j < 8; j++) ed[j] = edges[e + j];
        uint2 u[8];
        #pragma unroll
        for (int j = 0; j < 8; j++) u[j] = h2[(size_t)ed[j].x * 32 + lane];
        #pragma unroll
        for (int j = 0; j < 8; j++) {
            float w = __int_as_float(ed[j].y);
            float2 a = __half22float2(*(__half2*)&u[j].x);
            float2 b = __half22float2(*(__half2*)&u[j].y);
            acc.x = fmaf(w, a.x, acc.x); acc.y = fmaf(w, a.y, acc.y);
            acc.z = fmaf(w, b.x, acc.z); acc.w = fmaf(w, b.y, acc.w);
        }
    }
    if (e + 4 <= end) {
        int2 ed[4];
        #pragma unroll
        for (int j = 0; j < 4; j++) ed[j] = edges[e + j];
        uint2 u[4];
        #pragma unroll
        for (int j = 0; j < 4; j++) u[j] = h2[(size_t)ed[j].x * 32 + lane];
        #pragma unroll
        for (int j = 0; j < 4; j++) {
            float w = __int_as_float(ed[j].y);
            float2 a = __half22float2(*(__half2*)&u[j].x);
            float2 b = __half22float2(*(__half2*)&u[j].y);
            acc.x = fmaf(w, a.x, acc.x); acc.y = fmaf(w, a.y, acc.y);
            acc.z = fmaf(w, b.x, acc.z); acc.w = fmaf(w, b.y, acc.w);
        }
        e += 4;
    }
    for (; e < end; e++) {
        int2 ed = edges[e];
        float w = __int_as_float(ed.y);
        uint2 u = h2[(size_t)ed.x * 32 + lane];
        float2 a = __half22float2(*(__half2*)&u.x), b = __half22float2(*(__half2*)&u.y);
        acc.x = fmaf(w, a.x, acc.x); acc.y = fmaf(w, a.y, acc.y);
        acc.z = fmaf(w, b.x, acc.z); acc.w = fmaf(w, b.y, acc.w);
    }
    float ri = g_rin[r * NN + n];
    uint2 o;
    *(__half2*)&o.x = __floats2half2_rn(acc.x * ri, acc.y * ri);
    *(__half2*)&o.y = __floats2half2_rn(acc.z * ri, acc.w * ri);
    ((uint2*)g_zh)[((size_t)n * RR + r) * 32 + lane] = o;
}

// ---------------- fp16 tensor-core GEMM (m16n8k16 + ldmatrix) ----------------
__device__ __forceinline__ void mma_f16(float* c, const uint32_t* a,
                                        uint32_t b0, uint32_t b1) {
    asm volatile(
        "mma.sync.aligned.m16n8k16.row.col.f32.f16.f16.f32 "
        "{%0,%1,%2,%3}, {%4,%5,%6,%7}, {%8,%9}, {%0,%1,%2,%3};"
        : "+f"(c[0]), "+f"(c[1]), "+f"(c[2]), "+f"(c[3])
        : "r"(a[0]), "r"(a[1]), "r"(a[2]), "r"(a[3]), "r"(b0), "r"(b1));
}

__device__ __forceinline__ void ldsm_x4(uint32_t* d, uint32_t addr) {
    asm volatile("ldmatrix.sync.aligned.m8n8.x4.shared.b16 {%0,%1,%2,%3}, [%4];"
                 : "=r"(d[0]), "=r"(d[1]), "=r"(d[2]), "=r"(d[3]) : "r"(addr));
}

__device__ __forceinline__ void ldsm_x2(uint32_t& d0, uint32_t& d1, uint32_t addr) {
    asm volatile("ldmatrix.sync.aligned.m8n8.x2.shared.b16 {%0,%1}, [%2];"
                 : "=r"(d0), "=r"(d1) : "r"(addr));
}

// C[M,BN] = (A[M,K] @ Wt^T + sum_rows(bias)) * alpha.
// a_sel: -1 -> g_zh, 0/1 -> g_hh[a_sel].  wsel: 0..4 -> g_wt, 5 -> g_wtout.
// o_sel: 0/1 -> g_hh (fp16), 2 -> Cext (fp32).
template <int BN, int WN, int NT>
__global__ __launch_bounds__(NT)
void gemm_tc_kernel(int a_sel, int wsel,
                    const float* __restrict__ bias, int biasRows,
                    int o_sel, float* __restrict__ Cext,
                    int M, int K, float alpha, int leaky) {
    const int BM = 128, BK = 64, PAD = 8, LDW = BK + PAD;   // 72 halves
    const __half* A  = (a_sel < 0) ? g_zh : g_hh[a_sel];
    const __half* Wt = (wsel < 5) ? &g_wt[wsel][0][0] : &g_wtout[0][0];
    __half* Hout = (o_sel == 2) ? nullptr : g_hh[o_sel];

    __shared__ __half As[BM][LDW];
    __shared__ __half Bs[BN][LDW];

    int tid  = threadIdx.x;
    int wid  = tid >> 5;
    int lane = tid & 31;
    int g    = lane >> 2;
    int tg   = lane & 3;
    int wm   = wid / WN;
    int wn   = wid % WN;
    int blockRow = blockIdx.x * BM;

    uint32_t as_base = (uint32_t)__cvta_generic_to_shared(&As[0][0]);
    uint32_t bs_base = (uint32_t)__cvta_generic_to_shared(&Bs[0][0]);

    // ldmatrix lane addressing
    int a_row = wm * 64 + (lane & 15);       // + mt*16
    int a_col = (lane >> 4) * 8;             // + kb
    int b_row = wn * 32 + (lane & 7);        // + nt*8  (lanes 8-15 second matrix)
    int b_col = ((lane >> 3) & 1) * 8;       // + kb

    float acc[4][4][4];
    #pragma unroll
    for (int i = 0; i < 4; i++)
        #pragma unroll
        for (int j = 0; j < 4; j++)
            #pragma unroll
            for (int q = 0; q < 4; q++) acc[i][j][q] = 0.f;

    const int ASLOT = BM * (BK / 8);
    const int BSLOT = BN * (BK / 8);

    for (int k0 = 0; k0 < K; k0 += BK) {
        #pragma unroll
        for (int i = 0; i < ASLOT / NT; i++) {
            int v = tid + i * NT;
            int row = v >> 3, kq = v & 7;
            int gr = blockRow + row;
            uint4 val = make_uint4(0, 0, 0, 0);
            if (gr < M) val = *(const uint4*)(A + (size_t)gr * K + k0 + kq * 8);
            *(uint4*)&As[row][kq * 8] = val;
        }
        #pragma unroll
        for (int i = 0; i < BSLOT / NT; i++) {
            int v = tid + i * NT;
            int n = v >> 3, kq = v & 7;
            *(uint4*)&Bs[n][kq * 8] = *(const uint4*)(Wt + (size_t)n * K + k0 + kq * 8);
        }
        __syncthreads();

        #pragma unroll
        for (int kk = 0; kk < BK / 16; kk++) {
            int kb = kk * 16;
            uint32_t af[4][4];
            #pragma unroll
            for (int mt = 0; mt < 4; mt++) {
                uint32_t addr = as_base +
                    (uint32_t)(((a_row + mt * 16) * LDW + kb + a_col) * 2);
                ldsm_x4(af[mt], addr);
            }
            #pragma unroll
            for (int nt = 0; nt < 4; nt++) {
                uint32_t b0, b1;
                uint32_t addr = bs_base +
                    (uint32_t)(((b_row + nt * 8) * LDW + kb + b_col) * 2);
                ldsm_x2(b0, b1, addr);
                #pragma unroll
                for (int mt = 0; mt < 4; mt++)
                    mma_f16(acc[mt][nt], af[mt], b0, b1);
            }
        }
        __syncthreads();
    }

    // ---- epilogue ----
    float2 bs[4];
    #pragma unroll
    for (int nt = 0; nt < 4; nt++) {
        int col = wn * 32 + nt * 8 + tg * 2;
        float sx = 0.f, sy = 0.f;
        for (int rr = 0; rr < biasRows; rr++) {
            sx += bias[rr * BN + col];
            sy += bias[rr * BN + col + 1];
        }
        bs[nt].x = sx; bs[nt].y = sy;
    }
    #pragma unroll
    for (int mt = 0; mt < 4; mt++) {
        int r0 = blockRow + wm * 64 + mt * 16 + g;
        int r1 = r0 + 8;
        #pragma unroll
        for (int nt = 0; nt < 4; nt++) {
            int col = wn * 32 + nt * 8 + tg * 2;
            float v0 = (acc[mt][nt][0] + bs[nt].x) * alpha;
            float v1 = (acc[mt][nt][1] + bs[nt].y) * alpha;
            float v2 = (acc[mt][nt][2] + bs[nt].x) * alpha;
            float v3 = (acc[mt][nt][3] + bs[nt].y) * alpha;
            if (leaky) {
                if (v0 < 0.f) v0 *= 0.01f;
                if (v1 < 0.f) v1 *= 0.01f;
                if (v2 < 0.f) v2 *= 0.01f;
                if (v3 < 0.f) v3 *= 0.01f;
            }
            if (o_sel == 2) {
                if (r0 < M) *(float2*)(Cext + (size_t)r0 * BN + col) = make_float2(v0, v1);
                if (r1 < M) *(float2*)(Cext + (size_t)r1 * BN + col) = make_float2(v2, v3);
            } else {
                if (r0 < M) *(__half2*)(Hout + (size_t)r0 * BN + col) = __floats2half2_rn(v0, v1);
                if (r1 < M) *(__half2*)(Hout + (size_t)r1 * BN + col) = __floats2half2_rn(v2, v3);
            }
        }
    }
}

// ---------------- launcher ----------------
extern "C" void kernel_launch(void* const* d_in, const int* in_sizes, int n_in,
                              void* d_out, int out_size) {
    const float* x    = (const float*)d_in[0];
    const int*   esrc = (const int*)  d_in[1];
    const int*   edst = (const int*)  d_in[2];
    const float* W0   = (const float*)d_in[3];
    const float* b0   = (const float*)d_in[4];
    const float* Wl   = (const float*)d_in[5];
    const float* bl   = (const float*)d_in[6];
    const float* Wout = (const float*)d_in[7];
    const float* bout = (const float*)d_in[8];
    float* out = (float*)d_out;

    zero_deg_kernel<<<(RR * NN + 255) / 256, 256>>>();
    xconv_kernel<<<(NN * HIDD / 2 + 255) / 256, 256>>>(x);
    wconv_kernel<<<(5 * HIDD * KK + 64 * HIDD + 255) / 256, 256>>>(W0, Wl, Wout);
    deg_kernel<<<(RR * EE + 255) / 256, 256>>>(esrc, edst);
    rsqrt_kernel<<<(RR * NN + 255) / 256, 256>>>();
    scan1_kernel<<<dim3(NBLK, RR), SB>>>();
    scan2_kernel<<<RR, 256>>>();
    scan3_kernel<<<dim3(NBLK, RR), SB>>>();
    fill_kernel<<<(RR * EE + 255) / 256, 256>>>(esrc, edst);

    const int spmm_blocks = (RR * NN * 32 + 255) / 256;
    const int gemm_blocks = (NN + 127) / 128;   // 391
    const float inv_r = 1.0f / (float)RR;

    // layer 0: x -> h[0], leaky
    spmm_kernel<<<spmm_blocks, 256>>>(-1);
    gemm_tc_kernel<128, 4, 256><<<gemm_blocks, 256>>>(
        -1, 0, b0, RR, 0, nullptr, NN, KK, inv_r, 1);
    // layers 1..4
    int cur = 0;
    for (int l = 0; l < 4; l++) {
        spmm_kernel<<<spmm_blocks, 256>>>(cur);
        gemm_tc_kernel<128, 4, 256><<<gemm_blocks, 256>>>(
            -1, l + 1, bl + (size_t)l * RR * HIDD, RR,
            cur ^ 1, nullptr, NN, KK, inv_r, (l != 3) ? 1 : 0);
        cur ^= 1;
    }
    // final linear (fp32 out)
    gemm_tc_kernel<64, 2, 128><<<gemm_blocks, 128>>>(
        cur, 5, bout, 1, 2, out, NN, HIDD, 1.0f, 0);
}